// round 10
// baseline (speedup 1.0000x reference)
#include <cuda_runtime.h>
#include <cuda_fp16.h>

// DynamicRouting: B=128, IN=2048, OUT=32, POSE=4, 3 routing iterations.
// poses_out [B,32,4] followed by activations_out [B,32] in d_out.
//
// Pass 0 reads fp32 votes (DRAM, streaming) and writes an fp16 copy:
//   quads q=0..5  (i<768)  -> 192 KB of dynamic shared memory (per CTA)
//   quads q=6..15 (i>=768) -> 40 MB global scratch (evict_last, L2-resident)
// Hot passes 1-2 read 37.5% of votes from smem (29-cyc LDS) and the rest
// from L2. Softmax over the 32 lanes: integer REDUX.SUM on 2^10 fixed-point
// exp (identical arithmetic to the previous passing kernel).

#define NB 128
#define NI 2048
#define NO 32
#define NP 4
#define EPSF 1e-7f
#define NWARPS 32
#define NTHREADS 1024
#define NQUAD 16            // quads per thread: i = w + 32*(4q+h), h=0..3
#define SMQ 6               // quads 0..5 live in shared memory

// dynamic smem layout (bytes)
#define SM_PART 0                   // float4 part4[32][32]      (16 KB)
#define SM_VSH  (16 * 1024)         // float4 vsh4[2][32]        (1 KB)
#define SM_SSH  (17 * 1024)         // float  s_sh[128]          (0.5 KB)
#define SM_VOTE (20 * 1024)         // 12 chunks * 16 KB         (192 KB)
#define SM_CHUNK (16 * 1024)        // one chunk = 1024 threads * 16 B
#define SM_TOTAL (SM_VOTE + 2 * SMQ * SM_CHUNK)   // 212 KB

typedef unsigned long long u64;
typedef unsigned int u32;

// Global fp16 scratch for quads 6..15 (40 MB touched; layout as before).
__device__ __align__(32) __half vcache[(size_t)NB * NI * NO * NP];

__device__ __forceinline__ u32 h2_to_u32(__half2 h) {
    union { __half2 h; u32 u; } cvt; cvt.h = h; return cvt.u;
}
__device__ __forceinline__ __half2 u32_to_h2(u32 u) {
    union { u32 u; __half2 h; } cvt; cvt.u = u; return cvt.h;
}
__device__ __forceinline__ float ex2_fast(float x) {
    float r;
    asm("ex2.approx.ftz.f32 %0, %1;" : "=f"(r) : "f"(x));
    return r;
}

// fp32 vote load: read-only, streaming (evict_first).
__device__ __forceinline__ float4 ldg_stream(const float4* p, u64 pol) {
    float4 v;
    asm("ld.global.nc.L2::cache_hint.v4.f32 {%0,%1,%2,%3}, [%4], %5;"
        : "=f"(v.x), "=f"(v.y), "=f"(v.z), "=f"(v.w)
        : "l"(p), "l"(pol));
    return v;
}
// 16-byte scratch store with evict_last policy.
__device__ __forceinline__ void st_cache4(__half* p, u32 a, u32 b, u32 c, u32 d, u64 pol) {
    asm volatile("st.global.L2::cache_hint.v4.b32 [%0], {%1,%2,%3,%4}, %5;"
                 :: "l"(p), "r"(a), "r"(b), "r"(c), "r"(d), "l"(pol)
                 : "memory");
}
// 32-byte scratch load (LDG.256), evict_last.
__device__ __forceinline__ void ld_cache8(const __half* p, u32* r) {
    asm("ld.global.nc.L2::evict_last.v8.b32 {%0,%1,%2,%3,%4,%5,%6,%7}, [%8];"
        : "=r"(r[0]), "=r"(r[1]), "=r"(r[2]), "=r"(r[3]),
          "=r"(r[4]), "=r"(r[5]), "=r"(r[6]), "=r"(r[7])
        : "l"(p));
}

__global__ __launch_bounds__(NTHREADS, 1)
void routing_kernel(const float4* __restrict__ votes, float* __restrict__ out) {
    extern __shared__ char sm[];
    float4* part4 = (float4*)(sm + SM_PART);   // [32 warps][32 lanes]
    float4* vsh4  = (float4*)(sm + SM_VSH);    // [2][32]
    float*  s_sh  = (float*)(sm + SM_SSH);     // [128]

    const int b    = blockIdx.x;
    const int tid  = threadIdx.x;
    const int w    = tid >> 5;
    const int lane = tid & 31;      // lane == output-capsule index o

    u64 pol_first, pol_last;
    asm("createpolicy.fractional.L2::evict_first.b64 %0, 1.0;" : "=l"(pol_first));
    asm("createpolicy.fractional.L2::evict_last.b64 %0, 1.0;"  : "=l"(pol_last));

    const float4* vb = votes + (size_t)b * (NI * NO);
    // Global scratch slots (quads >= SMQ): slot(q) at ct + q*512 halves.
    __half* ct = vcache + (size_t)b * (NI * NO * NP)
                        + ((size_t)(w * NQUAD) * 32 + lane) * 16;
    // Shared vote chunks: chunk(c) base sm + SM_VOTE + c*SM_CHUNK, 16 B per tid.
    uint4* vsm = (uint4*)(sm + SM_VOTE) + tid;   // + chunk*1024 uint4's

    float4 v1 = make_float4(0.f, 0.f, 0.f, 0.f);
    float4 v2 = make_float4(0.f, 0.f, 0.f, 0.f);

#pragma unroll
    for (int it = 0; it < 3; ++it) {
        float ax = 0.f, ay = 0.f, az = 0.f, aw = 0.f;

        if (it == 0) {
            // fp32 streaming pass; uniform c = 1/32; write fp16 copies.
#pragma unroll 2
            for (int q = 0; q < NQUAD; ++q) {
                u32 pk[8];
#pragma unroll
                for (int h = 0; h < 4; ++h) {
                    const int i = w + 32 * (4 * q + h);
                    float4 vt = ldg_stream(&vb[i * NO + lane], pol_first);
                    pk[2 * h + 0] = h2_to_u32(__floats2half2_rn(vt.x, vt.y));
                    pk[2 * h + 1] = h2_to_u32(__floats2half2_rn(vt.z, vt.w));
                    ax += vt.x; ay += vt.y; az += vt.z; aw += vt.w;
                }
                if (q < SMQ) {
                    vsm[(2 * q + 0) * 1024] = make_uint4(pk[0], pk[1], pk[2], pk[3]);
                    vsm[(2 * q + 1) * 1024] = make_uint4(pk[4], pk[5], pk[6], pk[7]);
                } else {
                    __half* sp = ct + (size_t)q * 512;
                    st_cache4(sp,     pk[0], pk[1], pk[2], pk[3], pol_last);
                    st_cache4(sp + 8, pk[4], pk[5], pk[6], pk[7], pol_last);
                }
            }
            ax *= (1.0f / 32.0f); ay *= (1.0f / 32.0f);
            az *= (1.0f / 32.0f); aw *= (1.0f / 32.0f);
        } else {
            // Logit vector: it==1 -> v1;  it==2 -> v1+v2 (b accumulates).
            float4 wv;
            if (it == 1) wv = v1;
            else wv = make_float4(v1.x + v2.x, v1.y + v2.y,
                                  v1.z + v2.z, v1.w + v2.w);
            const float l2e = 1.44269504f;

#pragma unroll 2
            for (int q = 0; q < NQUAD; ++q) {
                u32 pk[8];
                if (q < SMQ) {
                    uint4 c0 = vsm[(2 * q + 0) * 1024];
                    uint4 c1 = vsm[(2 * q + 1) * 1024];
                    pk[0] = c0.x; pk[1] = c0.y; pk[2] = c0.z; pk[3] = c0.w;
                    pk[4] = c1.x; pk[5] = c1.y; pk[6] = c1.z; pk[7] = c1.w;
                } else {
                    ld_cache8(ct + (size_t)q * 512, pk);
                }
#pragma unroll
                for (int h = 0; h < 4; ++h) {
                    float2 f01 = __half22float2(u32_to_h2(pk[2 * h + 0]));
                    float2 f23 = __half22float2(u32_to_h2(pk[2 * h + 1]));
                    float bij = f01.x * wv.x + f01.y * wv.y
                              + f23.x * wv.z + f23.y * wv.w;
                    // e^bij * 2^10, fixed-point warp sum via integer REDUX.
                    float ef = ex2_fast(fmaf(bij, l2e, 10.0f));
                    u32   u  = __float2uint_rn(ef);
                    u32   s  = __reduce_add_sync(0xffffffffu, u);
                    float sf = fmaxf(__uint2float_rn(s), 1.0f);
                    float c  = __fdividef(ef, sf);   // 2^10 scale cancels
                    ax = fmaf(c, f01.x, ax);
                    ay = fmaf(c, f01.y, ay);
                    az = fmaf(c, f23.x, az);
                    aw = fmaf(c, f23.y, aw);
                }
            }
        }

        part4[w * NO + lane] = make_float4(ax, ay, az, aw);
        __syncthreads();

        // Reduce the 32 warp-partials: 128 threads, one per (o,p)
        if (tid < NO * NP) {
            const float* pf = (const float*)part4;
            float s = 0.f;
#pragma unroll
            for (int ww = 0; ww < NWARPS; ++ww)
                s += pf[ww * (NO * NP) + tid];
            s_sh[tid] = s;
        }
        __syncthreads();

        // Squash per output capsule (32 threads)
        if (tid < NO) {
            float sx = s_sh[tid * 4 + 0];
            float sy = s_sh[tid * 4 + 1];
            float sz = s_sh[tid * 4 + 2];
            float sw = s_sh[tid * 4 + 3];
            float n2 = sx * sx + sy * sy + sz * sz + sw * sw + EPSF;
            // v = (n2/(1+n2)) * s/sqrt(n2)  ==  s * sqrt(n2)/(1+n2)
            float f  = sqrtf(n2) / (1.0f + n2);
            float vx = sx * f, vy = sy * f, vz = sz * f, vw = sw * f;
            if (it < 2) {
                vsh4[it * NO + tid] = make_float4(vx, vy, vz, vw);
            } else {
                float* po = out + ((size_t)b * NO + tid) * NP;
                po[0] = vx; po[1] = vy; po[2] = vz; po[3] = vw;
                float a2 = vx * vx + vy * vy + vz * vz + vw * vw + EPSF;
                out[(size_t)NB * NO * NP + (size_t)b * NO + tid] = sqrtf(a2);
            }
        }
        __syncthreads();

        if (it == 0) v1 = vsh4[0 * NO + lane];
        else if (it == 1) v2 = vsh4[1 * NO + lane];
    }
}

extern "C" void kernel_launch(void* const* d_in, const int* in_sizes, int n_in,
                              void* d_out, int out_size) {
    const float4* votes = (const float4*)d_in[0];   // [B, I, O, P] fp32, 16B-aligned
    // d_in[1] = activations_in — unused by the reference computation
    float* out = (float*)d_out;
    cudaFuncSetAttribute(routing_kernel,
                         cudaFuncAttributeMaxDynamicSharedMemorySize, SM_TOTAL);
    routing_kernel<<<NB, NTHREADS, SM_TOTAL>>>(votes, out);
}